// round 12
// baseline (speedup 1.0000x reference)
#include <cuda_runtime.h>
#include <cuda_fp16.h>
#include <math.h>

#define DIN 128
#define HD  128
#define NH  4
#define NMAX 50000
#define ET_MAX 1700000   // E + N self loops
#define GMAX 256
#define KC   32          // GEMM K-chunk in smem

// ---------------- scratch (static device globals; no allocation) ----------------
__device__ __half g_h [NMAX * HD];    // GEMM output (pre-attention features), fp16 payload
__device__ float g_x2[NMAX * HD];     // layer output / next layer input
__device__ float g_as[NMAX * NH];
__device__ float g_ad[NMAX * NH];
__device__ int   g_deg[NMAX];
__device__ int   g_off[NMAX + 1];
__device__ int   g_cur[NMAX];
__device__ int   g_csr[ET_MAX];
__device__ float g_bn[2 * HD];        // col sum, col sumsq (zero-init, reset by bn_final)
__device__ float g_scale[HD];
__device__ float g_shift[HD];
__device__ float g_pool[GMAX * HD];   // zero-init, reset by head kernel
__device__ int   g_cnt[GMAX];

// ---------------- helpers ----------------
__device__ __forceinline__ float4 f4add(float4 a, float4 b) {
    return make_float4(a.x + b.x, a.y + b.y, a.z + b.z, a.w + b.w);
}
__device__ __forceinline__ float4 f4lrelu(float4 v) {
    return make_float4(fmaxf(v.x, 0.2f * v.x), fmaxf(v.y, 0.2f * v.y),
                       fmaxf(v.z, 0.2f * v.z), fmaxf(v.w, 0.2f * v.w));
}
__device__ __forceinline__ unsigned h2_as_u32(__half2 h) {
    return *reinterpret_cast<unsigned*>(&h);
}
__device__ __forceinline__ float tf32_of(float v) {
    unsigned o;
    asm("cvt.rna.tf32.f32 %0, %1;" : "=r"(o) : "f"(v));
    return __uint_as_float(o);
}
__device__ __forceinline__ void mma_tf32(float c[4], const float a[4], float b0, float b1) {
    asm volatile(
        "mma.sync.aligned.m16n8k8.row.col.f32.tf32.tf32.f32 "
        "{%0,%1,%2,%3}, {%4,%5,%6,%7}, {%8,%9}, {%0,%1,%2,%3};"
        : "+f"(c[0]), "+f"(c[1]), "+f"(c[2]), "+f"(c[3])
        : "r"(__float_as_uint(a[0])), "r"(__float_as_uint(a[1])),
          "r"(__float_as_uint(a[2])), "r"(__float_as_uint(a[3])),
          "r"(__float_as_uint(b0)),   "r"(__float_as_uint(b1)));
}

// ---------------- CSR build ----------------
__global__ void count_kernel(const int* __restrict__ ei, int E, int n) {
    int i = blockIdx.x * blockDim.x + threadIdx.x;
    if (i >= E + n) return;
    int d = (i < E) ? ei[E + i] : (i - E);
    atomicAdd(&g_deg[d], 1);
}

// single-block exclusive scan of g_deg -> g_off, 4 elems/thread.
// Also zeroes g_deg (for next call) and g_cur (for fill later this call).
__global__ void scan_kernel(int n) {
    __shared__ int warp_sums[32];
    __shared__ int carry_sh;
    int t = threadIdx.x;
    int lane = t & 31, wid = t >> 5;
    if (t == 0) { carry_sh = 0; g_off[0] = 0; }
    __syncthreads();
    for (int base = 0; base < n; base += 4096) {
        int i = base + t * 4;
        int v0 = 0, v1 = 0, v2 = 0, v3 = 0;
        if (i + 3 < n) {
            int4 v = *(const int4*)&g_deg[i];
            v0 = v.x; v1 = v.y; v2 = v.z; v3 = v.w;
        } else {
            if (i     < n) v0 = g_deg[i];
            if (i + 1 < n) v1 = g_deg[i + 1];
            if (i + 2 < n) v2 = g_deg[i + 2];
            if (i + 3 < n) v3 = g_deg[i + 3];
        }
        int p0 = v0, p1 = p0 + v1, p2 = p1 + v2, p3 = p2 + v3;
        int x = p3;
        #pragma unroll
        for (int o = 1; o < 32; o <<= 1) {
            int y = __shfl_up_sync(0xffffffffu, x, o);
            if (lane >= o) x += y;
        }
        if (lane == 31) warp_sums[wid] = x;
        __syncthreads();
        if (wid == 0) {
            int w = warp_sums[lane];
            #pragma unroll
            for (int o = 1; o < 32; o <<= 1) {
                int y = __shfl_up_sync(0xffffffffu, w, o);
                if (lane >= o) w += y;
            }
            warp_sums[lane] = w;
        }
        __syncthreads();
        int woff = (wid > 0) ? warp_sums[wid - 1] : 0;
        int excl = carry_sh + woff + (x - p3);
        if (i     < n) g_off[i + 1] = excl + p0;
        if (i + 1 < n) g_off[i + 2] = excl + p1;
        if (i + 2 < n) g_off[i + 3] = excl + p2;
        if (i + 3 < n) g_off[i + 4] = excl + p3;
        int4 z4 = make_int4(0, 0, 0, 0);
        if (i + 3 < n) {
            *(int4*)&g_deg[i] = z4;
            *(int4*)&g_cur[i] = z4;
        } else {
            for (int q = 0; q < 4; q++)
                if (i + q < n) { g_deg[i + q] = 0; g_cur[i + q] = 0; }
        }
        __syncthreads();
        if (t == 1023) carry_sh = excl + p3;
        __syncthreads();
    }
}

__global__ void fill_kernel(const int* __restrict__ ei, int E, int n) {
    int i = blockIdx.x * blockDim.x + threadIdx.x;
    if (i >= E + n) return;
    int s, d;
    if (i < E) { s = __ldcs(&ei[i]); d = __ldcs(&ei[E + i]); }
    else       { s = d = i - E; }
    int pos = g_off[d] + atomicAdd(&g_cur[d], 1);
    g_csr[pos] = s;
}

// ---------------- tensor-core GEMM (tf32 mma.sync): g_h[M,128](fp16) = A @ B ----------------
// 64-row tiles, 8 warps of 16x64.
__global__ __launch_bounds__(256, 3) void gemm_tc(const float* __restrict__ Ain,
                                                  const float* __restrict__ B,
                                                  int M, int use_x2, int use_scale,
                                                  const float* __restrict__ a_src,
                                                  const float* __restrict__ a_dst) {
    const float* A = use_x2 ? (const float*)g_x2 : Ain;
    __shared__ float As[64][KC + 4];
    __shared__ float Bs[KC][132];
    __shared__ float sA[64][NH];
    __shared__ float sD[64][NH];

    int tid  = threadIdx.x;
    int lane = tid & 31;
    int warp = tid >> 5;
    int warpM = warp >> 1;
    int warpN = warp & 1;
    int row0 = blockIdx.x * 64;

    sA[tid >> 2][tid & 3] = 0.f;
    sD[tid >> 2][tid & 3] = 0.f;

    float c[8][4];
    #pragma unroll
    for (int j = 0; j < 8; j++)
        #pragma unroll
        for (int q = 0; q < 4; q++) c[j][q] = 0.f;

    for (int kc = 0; kc < 128; kc += KC) {
        #pragma unroll
        for (int l = 0; l < 2; l++) {
            int slot = tid * 2 + l;
            int r  = slot >> 3;
            int kq = slot & 7;
            float4 v = make_float4(0.f, 0.f, 0.f, 0.f);
            if (row0 + r < M) {
                v = *(const float4*)(A + (row0 + r) * 128 + kc + kq * 4);
                if (use_scale) {
                    float4 sc = *(const float4*)(g_scale + kc + kq * 4);
                    float4 sf = *(const float4*)(g_shift + kc + kq * 4);
                    v.x = fmaf(v.x, sc.x, sf.x);
                    v.y = fmaf(v.y, sc.y, sf.y);
                    v.z = fmaf(v.z, sc.z, sf.z);
                    v.w = fmaf(v.w, sc.w, sf.w);
                }
            }
            v.x = tf32_of(v.x); v.y = tf32_of(v.y); v.z = tf32_of(v.z); v.w = tf32_of(v.w);
            *(float4*)&As[r][kq * 4] = v;
        }
        #pragma unroll
        for (int i = 0; i < 4; i++) {
            int slot = tid + i * 256;
            int k  = slot >> 5;
            int nq = slot & 31;
            float4 v = *(const float4*)(B + (kc + k) * 128 + nq * 4);
            v.x = tf32_of(v.x); v.y = tf32_of(v.y); v.z = tf32_of(v.z); v.w = tf32_of(v.w);
            *(float4*)&Bs[k][nq * 4] = v;
        }
        __syncthreads();

        #pragma unroll
        for (int ks = 0; ks < KC; ks += 8) {
            float a[4];
            int ar = warpM * 16 + (lane >> 2);
            int ac = ks + (lane & 3);
            a[0] = As[ar][ac];
            a[1] = As[ar + 8][ac];
            a[2] = As[ar][ac + 4];
            a[3] = As[ar + 8][ac + 4];
            #pragma unroll
            for (int j = 0; j < 8; j++) {
                int bn = warpN * 64 + j * 8 + (lane >> 2);
                float b0 = Bs[ks + (lane & 3)][bn];
                float b1 = Bs[ks + (lane & 3) + 4][bn];
                mma_tf32(c[j], a, b0, b1);
            }
        }
        __syncthreads();
    }

    {
        int lr0 = warpM * 16 + (lane >> 2);
        int lr1 = lr0 + 8;
        int rr0 = row0 + lr0;
        int rr1 = row0 + lr1;
        float ps0[2] = {0.f, 0.f}, pd0[2] = {0.f, 0.f};
        float ps1[2] = {0.f, 0.f}, pd1[2] = {0.f, 0.f};
        #pragma unroll
        for (int j = 0; j < 8; j++) {
            int cn = warpN * 64 + j * 8 + (lane & 3) * 2;
            float s0 = a_src[cn], s1 = a_src[cn + 1];
            float d0 = a_dst[cn], d1 = a_dst[cn + 1];
            int hh = j >> 2;
            ps0[hh] = fmaf(c[j][0], s0, fmaf(c[j][1], s1, ps0[hh]));
            pd0[hh] = fmaf(c[j][0], d0, fmaf(c[j][1], d1, pd0[hh]));
            ps1[hh] = fmaf(c[j][2], s0, fmaf(c[j][3], s1, ps1[hh]));
            pd1[hh] = fmaf(c[j][2], d0, fmaf(c[j][3], d1, pd1[hh]));
            if (rr0 < M)
                *(__half2*)(&g_h[rr0 * 128 + cn]) = __floats2half2_rn(c[j][0], c[j][1]);
            if (rr1 < M)
                *(__half2*)(&g_h[rr1 * 128 + cn]) = __floats2half2_rn(c[j][2], c[j][3]);
        }
        int h0 = warpN * 2;
        if (rr0 < M) {
            atomicAdd(&sA[lr0][h0],     ps0[0]);
            atomicAdd(&sA[lr0][h0 + 1], ps0[1]);
            atomicAdd(&sD[lr0][h0],     pd0[0]);
            atomicAdd(&sD[lr0][h0 + 1], pd0[1]);
        }
        if (rr1 < M) {
            atomicAdd(&sA[lr1][h0],     ps1[0]);
            atomicAdd(&sA[lr1][h0 + 1], ps1[1]);
            atomicAdd(&sD[lr1][h0],     pd1[0]);
            atomicAdd(&sD[lr1][h0 + 1], pd1[1]);
        }
    }
    __syncthreads();
    {
        int r = tid >> 2, h = tid & 3;
        if (row0 + r < M) {
            g_as[(row0 + r) * NH + h] = sA[r][h];
            g_ad[(row0 + r) * NH + h] = sD[r][h];
        }
    }
}

// ---------------- GAT aggregation: warp/node, double-buffered pipelined staging ----------------
// Pipeline: csr index prefetched one chunk ahead; g_as gather for chunk c+1 issued
// BEFORE consuming chunk c (gather latency hidden under consume); exp + smem store after.
__global__ __launch_bounds__(256) void gat_agg(const float* __restrict__ bias, int n) {
    __shared__ int   s_idx[2][8][32];
    __shared__ float s_ex [2][8][128];
    __shared__ float sbn[256];

    int tid  = threadIdx.x;
    int w    = tid >> 5;
    int lane = tid & 31;
    int head = lane >> 3;

    sbn[tid] = 0.f;
    __syncthreads();

    int d = blockIdx.x * 8 + w;
    if (d < n) {
        int beg = g_off[d];
        int deg = g_off[d + 1] - beg;
        float4 adv = ((const float4*)g_ad)[d];

        float4 sumex = make_float4(0.f, 0.f, 0.f, 0.f);
        float acc0 = 0.f, acc1 = 0.f, acc2 = 0.f, acc3 = 0.f;

        int nchunks = (deg + 31) >> 5;

        // prologue: chunk 0 fully staged; chunk 1 csr index prefetched
        bool v0 = lane < deg;
        int  sc0 = 0;
        if (v0) sc0 = __ldcs(&g_csr[beg + lane]);
        bool v1 = (32 + lane) < deg;
        int  sn = 0;
        if (v1) sn = __ldcs(&g_csr[beg + 32 + lane]);
        if (v0) {
            float4 e = f4lrelu(f4add(((const float4*)g_as)[sc0], adv));
            float4 ex = make_float4(__expf(e.x), __expf(e.y), __expf(e.z), __expf(e.w));
            sumex = f4add(sumex, ex);
            s_idx[0][w][lane] = sc0;
            *(float4*)&s_ex[0][w][lane * 4] = ex;
        }

        for (int c = 0; c < nchunks; c++) {
            __syncwarp();
            int buf = c & 1;
            // issue gather for chunk c+1 (independent of consume below)
            bool vn = ((c + 1) * 32 + lane) < deg;
            float4 asn = make_float4(0.f, 0.f, 0.f, 0.f);
            if (vn) asn = ((const float4*)g_as)[sn];
            // prefetch csr for chunk c+2
            bool vnn = ((c + 2) * 32 + lane) < deg;
            int snn = 0;
            if (vnn) snn = __ldcs(&g_csr[beg + (c + 2) * 32 + lane]);

            // consume chunk c (hides the gather latency)
            int cnt = min(32, deg - c * 32);
            const int*   ip = &s_idx[buf][w][0];
            const float* ep = &s_ex[buf][w][0];
            if (cnt == 32) {
                #pragma unroll 8
                for (int j = 0; j < 32; j++) {
                    int   s  = ip[j];
                    float wt = ep[j * 4 + head];
                    uint2 pk = __ldcg((const uint2*)(&g_h[s * HD + lane * 4]));
                    __half2* hp = reinterpret_cast<__half2*>(&pk);
                    float2 f0 = __half22float2(hp[0]);
                    float2 f1 = __half22float2(hp[1]);
                    acc0 = fmaf(f0.x, wt, acc0);
                    acc1 = fmaf(f0.y, wt, acc1);
                    acc2 = fmaf(f1.x, wt, acc2);
                    acc3 = fmaf(f1.y, wt, acc3);
                }
            } else {
                #pragma unroll 4
                for (int j = 0; j < cnt; j++) {
                    int   s  = ip[j];
                    float wt = ep[j * 4 + head];
                    uint2 pk = __ldcg((const uint2*)(&g_h[s * HD + lane * 4]));
                    __half2* hp = reinterpret_cast<__half2*>(&pk);
                    float2 f0 = __half22float2(hp[0]);
                    float2 f1 = __half22float2(hp[1]);
                    acc0 = fmaf(f0.x, wt, acc0);
                    acc1 = fmaf(f0.y, wt, acc1);
                    acc2 = fmaf(f1.x, wt, acc2);
                    acc3 = fmaf(f1.y, wt, acc3);
                }
            }

            // stage chunk c+1 into the other buffer
            if (vn) {
                float4 e = f4lrelu(f4add(asn, adv));
                float4 ex = make_float4(__expf(e.x), __expf(e.y), __expf(e.z), __expf(e.w));
                sumex = f4add(sumex, ex);
                s_idx[buf ^ 1][w][lane] = sn;
                *(float4*)&s_ex[buf ^ 1][w][lane * 4] = ex;
            }
            sn = snn;
        }

        #pragma unroll
        for (int o = 16; o; o >>= 1) {
            sumex.x += __shfl_xor_sync(0xffffffffu, sumex.x, o);
            sumex.y += __shfl_xor_sync(0xffffffffu, sumex.y, o);
            sumex.z += __shfl_xor_sync(0xffffffffu, sumex.z, o);
            sumex.w += __shfl_xor_sync(0xffffffffu, sumex.w, o);
        }
        float sv = (head == 0) ? sumex.x : (head == 1) ? sumex.y
                 : (head == 2) ? sumex.z : sumex.w;
        float inv = 1.0f / (sv + 1e-16f);

        float4 b = *(const float4*)(bias + lane * 4);
        float o0 = fmaxf(fmaf(acc0, inv, b.x), 0.f);
        float o1 = fmaxf(fmaf(acc1, inv, b.y), 0.f);
        float o2 = fmaxf(fmaf(acc2, inv, b.z), 0.f);
        float o3 = fmaxf(fmaf(acc3, inv, b.w), 0.f);
        __stcs((float4*)(&g_x2[d * HD + lane * 4]), make_float4(o0, o1, o2, o3));

        int c = lane * 4;
        atomicAdd(&sbn[c + 0], o0);
        atomicAdd(&sbn[c + 1], o1);
        atomicAdd(&sbn[c + 2], o2);
        atomicAdd(&sbn[c + 3], o3);
        atomicAdd(&sbn[128 + c + 0], o0 * o0);
        atomicAdd(&sbn[128 + c + 1], o1 * o1);
        atomicAdd(&sbn[128 + c + 2], o2 * o2);
        atomicAdd(&sbn[128 + c + 3], o3 * o3);
    }
    __syncthreads();
    atomicAdd(&g_bn[tid], sbn[tid]);
}

// ---------------- BN finalize ----------------
__global__ void bn_final(const float* __restrict__ gamma, const float* __restrict__ beta, int n) {
    int c = threadIdx.x;
    float fn = (float)n;
    float mu  = g_bn[c] / fn;
    float var = g_bn[HD + c] / fn - mu * mu;
    float inv = rsqrtf(var + 1e-5f);
    float sc  = gamma[c] * inv;
    g_scale[c] = sc;
    g_shift[c] = beta[c] - mu * sc;
    g_bn[c] = 0.f;
    g_bn[HD + c] = 0.f;
}

// ---------------- pooling: batch sorted -> segmented register accumulation ----------------
__global__ __launch_bounds__(128) void pool_kernel(const int* __restrict__ batch, int n, int chunk) {
    int i0 = blockIdx.x * chunk;
    if (i0 >= n) return;
    int i1 = min(n, i0 + chunk);
    int t  = threadIdx.x;
    float acc = 0.f;
    int cur = batch[i0];
    int run = 0;
    for (int i = i0; i < i1; i++) {
        int g = batch[i];
        if (g != cur) {
            atomicAdd(&g_pool[cur * HD + t], acc);
            if (t == 0) atomicAdd(&g_cnt[cur], run);
            acc = 0.f; run = 0; cur = g;
        }
        acc += __ldcs(&g_x2[i * HD + t]);
        run++;
    }
    atomicAdd(&g_pool[cur * HD + t], acc);
    if (t == 0) atomicAdd(&g_cnt[cur], run);
}

// ---------------- MLP head ----------------
__global__ __launch_bounds__(128) void head_kernel(const float* __restrict__ L1W,
                                                   const float* __restrict__ L1b,
                                                   const float* __restrict__ L2W,
                                                   const float* __restrict__ L2b,
                                                   float* __restrict__ out) {
    int g = blockIdx.x, t = threadIdx.x;
    __shared__ float p[128], r0[128], r1[128];
    int c = g_cnt[g];
    float denom = (float)(c > 0 ? c : 1);
    p[t] = fmaf(g_pool[g * HD + t] / denom, g_scale[t], g_shift[t]);
    g_pool[g * HD + t] = 0.f;
    if (t == 0) g_cnt[g] = 0;
    __syncthreads();
    float acc = L1b[t];
    #pragma unroll 8
    for (int k = 0; k < 128; k++)
        acc = fmaf(p[k], L1W[k * HD + t], acc);
    float z = fmaxf(acc, 0.f);
    r0[t] = z * L2W[t * 2 + 0];
    r1[t] = z * L2W[t * 2 + 1];
    __syncthreads();
    for (int o = 64; o; o >>= 1) {
        if (t < o) { r0[t] += r0[t + o]; r1[t] += r1[t + o]; }
        __syncthreads();
    }
    if (t == 0) {
        out[g * 2 + 0] = r0[0] + L2b[0];
        out[g * 2 + 1] = r1[0] + L2b[1];
    }
}

// ---------------- launch ----------------
extern "C" void kernel_launch(void* const* d_in, const int* in_sizes, int n_in,
                              void* d_out, int out_size) {
    const float* x    = (const float*)d_in[0];
    const int*   ei   = (const int*)  d_in[1];
    const int*   batch= (const int*)  d_in[2];
    const float* W1   = (const float*)d_in[3];
    const float* a1s  = (const float*)d_in[4];
    const float* a1d  = (const float*)d_in[5];
    const float* b1   = (const float*)d_in[6];
    const float* bn1g = (const float*)d_in[7];
    const float* bn1b = (const float*)d_in[8];
    const float* W2   = (const float*)d_in[9];
    const float* a2s  = (const float*)d_in[10];
    const float* a2d  = (const float*)d_in[11];
    const float* b2   = (const float*)d_in[12];
    const float* bn2g = (const float*)d_in[13];
    const float* bn2b = (const float*)d_in[14];
    const float* L1W  = (const float*)d_in[15];
    const float* L1b  = (const float*)d_in[16];
    const float* L2W  = (const float*)d_in[17];
    const float* L2b  = (const float*)d_in[18];

    int n = in_sizes[0] / HD;
    int E = in_sizes[1] / 2;
    int G = out_size / 2;
    int ET = E + n;

    count_kernel<<<(ET + 255) / 256, 256>>>(ei, E, n);
    scan_kernel <<<1, 1024>>>(n);
    fill_kernel <<<(ET + 255) / 256, 256>>>(ei, E, n);

    int gb  = (n + 63) / 64;
    int agb = (n + 7) / 8;

    gemm_tc <<<gb, 256>>>(x, W1, n, 0, 0, a1s, a1d);
    gat_agg <<<agb, 256>>>(b1, n);
    bn_final<<<1, 128>>>(bn1g, bn1b, n);

    gemm_tc <<<gb, 256>>>(nullptr, W2, n, 1, 1, a2s, a2d);
    gat_agg <<<agb, 256>>>(b2, n);
    bn_final<<<1, 128>>>(bn2g, bn2b, n);

    pool_kernel<<<(n + 255) / 256, 128>>>(batch, n, 256);
    head_kernel<<<G, 128>>>(L1W, L1b, L2W, L2b, (float*)d_out);
}

// round 13
// speedup vs baseline: 1.0271x; 1.0271x over previous
#include <cuda_runtime.h>
#include <cuda_fp16.h>
#include <math.h>

#define DIN 128
#define HD  128
#define NH  4
#define NMAX 50000
#define ET_MAX 1700000   // E + N self loops
#define GMAX 256
#define KC   32          // GEMM K-chunk in smem

// ---------------- scratch (static device globals; no allocation) ----------------
__device__ __half g_h [NMAX * HD];    // GEMM output (pre-attention features), fp16 payload
__device__ float g_x2[NMAX * HD];     // layer output / next layer input
__device__ float g_as[NMAX * NH];
__device__ float g_ad[NMAX * NH];
__device__ int   g_deg[NMAX];
__device__ int   g_off[NMAX + 1];
__device__ int   g_cur[NMAX];
__device__ int   g_csr[ET_MAX];
__device__ float g_bn[2 * HD];        // col sum, col sumsq (zero-init, reset by bn_final)
__device__ float g_scale[HD];
__device__ float g_shift[HD];
__device__ float g_pool[GMAX * HD];   // zero-init, reset by head kernel
__device__ int   g_cnt[GMAX];

// ---------------- helpers ----------------
__device__ __forceinline__ float4 f4add(float4 a, float4 b) {
    return make_float4(a.x + b.x, a.y + b.y, a.z + b.z, a.w + b.w);
}
__device__ __forceinline__ float4 f4lrelu(float4 v) {
    return make_float4(fmaxf(v.x, 0.2f * v.x), fmaxf(v.y, 0.2f * v.y),
                       fmaxf(v.z, 0.2f * v.z), fmaxf(v.w, 0.2f * v.w));
}
__device__ __forceinline__ unsigned h2_as_u32(__half2 h) {
    return *reinterpret_cast<unsigned*>(&h);
}
__device__ __forceinline__ float tf32_of(float v) {
    unsigned o;
    asm("cvt.rna.tf32.f32 %0, %1;" : "=r"(o) : "f"(v));
    return __uint_as_float(o);
}
__device__ __forceinline__ void mma_tf32(float c[4], const float a[4], float b0, float b1) {
    asm volatile(
        "mma.sync.aligned.m16n8k8.row.col.f32.tf32.tf32.f32 "
        "{%0,%1,%2,%3}, {%4,%5,%6,%7}, {%8,%9}, {%0,%1,%2,%3};"
        : "+f"(c[0]), "+f"(c[1]), "+f"(c[2]), "+f"(c[3])
        : "r"(__float_as_uint(a[0])), "r"(__float_as_uint(a[1])),
          "r"(__float_as_uint(a[2])), "r"(__float_as_uint(a[3])),
          "r"(__float_as_uint(b0)),   "r"(__float_as_uint(b1)));
}

// ---------------- CSR build ----------------
__global__ void count_kernel(const int* __restrict__ ei, int E, int n) {
    int i = blockIdx.x * blockDim.x + threadIdx.x;
    if (i >= E + n) return;
    int d = (i < E) ? ei[E + i] : (i - E);
    atomicAdd(&g_deg[d], 1);
}

// single-block exclusive scan of g_deg -> g_off, 4 elems/thread.
// Also zeroes g_deg (for next call) and g_cur (for fill later this call).
__global__ void scan_kernel(int n) {
    __shared__ int warp_sums[32];
    __shared__ int carry_sh;
    int t = threadIdx.x;
    int lane = t & 31, wid = t >> 5;
    if (t == 0) { carry_sh = 0; g_off[0] = 0; }
    __syncthreads();
    for (int base = 0; base < n; base += 4096) {
        int i = base + t * 4;
        int v0 = 0, v1 = 0, v2 = 0, v3 = 0;
        if (i + 3 < n) {
            int4 v = *(const int4*)&g_deg[i];
            v0 = v.x; v1 = v.y; v2 = v.z; v3 = v.w;
        } else {
            if (i     < n) v0 = g_deg[i];
            if (i + 1 < n) v1 = g_deg[i + 1];
            if (i + 2 < n) v2 = g_deg[i + 2];
            if (i + 3 < n) v3 = g_deg[i + 3];
        }
        int p0 = v0, p1 = p0 + v1, p2 = p1 + v2, p3 = p2 + v3;
        int x = p3;
        #pragma unroll
        for (int o = 1; o < 32; o <<= 1) {
            int y = __shfl_up_sync(0xffffffffu, x, o);
            if (lane >= o) x += y;
        }
        if (lane == 31) warp_sums[wid] = x;
        __syncthreads();
        if (wid == 0) {
            int w = warp_sums[lane];
            #pragma unroll
            for (int o = 1; o < 32; o <<= 1) {
                int y = __shfl_up_sync(0xffffffffu, w, o);
                if (lane >= o) w += y;
            }
            warp_sums[lane] = w;
        }
        __syncthreads();
        int woff = (wid > 0) ? warp_sums[wid - 1] : 0;
        int excl = carry_sh + woff + (x - p3);
        if (i     < n) g_off[i + 1] = excl + p0;
        if (i + 1 < n) g_off[i + 2] = excl + p1;
        if (i + 2 < n) g_off[i + 3] = excl + p2;
        if (i + 3 < n) g_off[i + 4] = excl + p3;
        int4 z4 = make_int4(0, 0, 0, 0);
        if (i + 3 < n) {
            *(int4*)&g_deg[i] = z4;
            *(int4*)&g_cur[i] = z4;
        } else {
            for (int q = 0; q < 4; q++)
                if (i + q < n) { g_deg[i + q] = 0; g_cur[i + q] = 0; }
        }
        __syncthreads();
        if (t == 1023) carry_sh = excl + p3;
        __syncthreads();
    }
}

__global__ void fill_kernel(const int* __restrict__ ei, int E, int n) {
    int i = blockIdx.x * blockDim.x + threadIdx.x;
    if (i >= E + n) return;
    int s, d;
    if (i < E) { s = __ldcs(&ei[i]); d = __ldcs(&ei[E + i]); }
    else       { s = d = i - E; }
    int pos = g_off[d] + atomicAdd(&g_cur[d], 1);
    g_csr[pos] = s;
}

// ---------------- tensor-core GEMM (tf32 mma.sync): g_h[M,128](fp16) = A @ B ----------------
// 64-row tiles, 8 warps of 16x64.
__global__ __launch_bounds__(256, 3) void gemm_tc(const float* __restrict__ Ain,
                                                  const float* __restrict__ B,
                                                  int M, int use_x2, int use_scale,
                                                  const float* __restrict__ a_src,
                                                  const float* __restrict__ a_dst) {
    const float* A = use_x2 ? (const float*)g_x2 : Ain;
    __shared__ float As[64][KC + 4];
    __shared__ float Bs[KC][132];
    __shared__ float sA[64][NH];
    __shared__ float sD[64][NH];

    int tid  = threadIdx.x;
    int lane = tid & 31;
    int warp = tid >> 5;
    int warpM = warp >> 1;
    int warpN = warp & 1;
    int row0 = blockIdx.x * 64;

    sA[tid >> 2][tid & 3] = 0.f;
    sD[tid >> 2][tid & 3] = 0.f;

    float c[8][4];
    #pragma unroll
    for (int j = 0; j < 8; j++)
        #pragma unroll
        for (int q = 0; q < 4; q++) c[j][q] = 0.f;

    for (int kc = 0; kc < 128; kc += KC) {
        #pragma unroll
        for (int l = 0; l < 2; l++) {
            int slot = tid * 2 + l;
            int r  = slot >> 3;
            int kq = slot & 7;
            float4 v = make_float4(0.f, 0.f, 0.f, 0.f);
            if (row0 + r < M) {
                v = *(const float4*)(A + (row0 + r) * 128 + kc + kq * 4);
                if (use_scale) {
                    float4 sc = *(const float4*)(g_scale + kc + kq * 4);
                    float4 sf = *(const float4*)(g_shift + kc + kq * 4);
                    v.x = fmaf(v.x, sc.x, sf.x);
                    v.y = fmaf(v.y, sc.y, sf.y);
                    v.z = fmaf(v.z, sc.z, sf.z);
                    v.w = fmaf(v.w, sc.w, sf.w);
                }
            }
            v.x = tf32_of(v.x); v.y = tf32_of(v.y); v.z = tf32_of(v.z); v.w = tf32_of(v.w);
            *(float4*)&As[r][kq * 4] = v;
        }
        #pragma unroll
        for (int i = 0; i < 4; i++) {
            int slot = tid + i * 256;
            int k  = slot >> 5;
            int nq = slot & 31;
            float4 v = *(const float4*)(B + (kc + k) * 128 + nq * 4);
            v.x = tf32_of(v.x); v.y = tf32_of(v.y); v.z = tf32_of(v.z); v.w = tf32_of(v.w);
            *(float4*)&Bs[k][nq * 4] = v;
        }
        __syncthreads();

        #pragma unroll
        for (int ks = 0; ks < KC; ks += 8) {
            float a[4];
            int ar = warpM * 16 + (lane >> 2);
            int ac = ks + (lane & 3);
            a[0] = As[ar][ac];
            a[1] = As[ar + 8][ac];
            a[2] = As[ar][ac + 4];
            a[3] = As[ar + 8][ac + 4];
            #pragma unroll
            for (int j = 0; j < 8; j++) {
                int bn = warpN * 64 + j * 8 + (lane >> 2);
                float b0 = Bs[ks + (lane & 3)][bn];
                float b1 = Bs[ks + (lane & 3) + 4][bn];
                mma_tf32(c[j], a, b0, b1);
            }
        }
        __syncthreads();
    }

    {
        int lr0 = warpM * 16 + (lane >> 2);
        int lr1 = lr0 + 8;
        int rr0 = row0 + lr0;
        int rr1 = row0 + lr1;
        float ps0[2] = {0.f, 0.f}, pd0[2] = {0.f, 0.f};
        float ps1[2] = {0.f, 0.f}, pd1[2] = {0.f, 0.f};
        #pragma unroll
        for (int j = 0; j < 8; j++) {
            int cn = warpN * 64 + j * 8 + (lane & 3) * 2;
            float s0 = a_src[cn], s1 = a_src[cn + 1];
            float d0 = a_dst[cn], d1 = a_dst[cn + 1];
            int hh = j >> 2;
            ps0[hh] = fmaf(c[j][0], s0, fmaf(c[j][1], s1, ps0[hh]));
            pd0[hh] = fmaf(c[j][0], d0, fmaf(c[j][1], d1, pd0[hh]));
            ps1[hh] = fmaf(c[j][2], s0, fmaf(c[j][3], s1, ps1[hh]));
            pd1[hh] = fmaf(c[j][2], d0, fmaf(c[j][3], d1, pd1[hh]));
            if (rr0 < M)
                *(__half2*)(&g_h[rr0 * 128 + cn]) = __floats2half2_rn(c[j][0], c[j][1]);
            if (rr1 < M)
                *(__half2*)(&g_h[rr1 * 128 + cn]) = __floats2half2_rn(c[j][2], c[j][3]);
        }
        int h0 = warpN * 2;
        if (rr0 < M) {
            atomicAdd(&sA[lr0][h0],     ps0[0]);
            atomicAdd(&sA[lr0][h0 + 1], ps0[1]);
            atomicAdd(&sD[lr0][h0],     pd0[0]);
            atomicAdd(&sD[lr0][h0 + 1], pd0[1]);
        }
        if (rr1 < M) {
            atomicAdd(&sA[lr1][h0],     ps1[0]);
            atomicAdd(&sA[lr1][h0 + 1], ps1[1]);
            atomicAdd(&sD[lr1][h0],     pd1[0]);
            atomicAdd(&sD[lr1][h0 + 1], pd1[1]);
        }
    }
    __syncthreads();
    {
        int r = tid >> 2, h = tid & 3;
        if (row0 + r < M) {
            g_as[(row0 + r) * NH + h] = sA[r][h];
            g_ad[(row0 + r) * NH + h] = sD[r][h];
        }
    }
}

// ---------------- GAT aggregation: one WARP per dst node + fused BN stats ----------------
__global__ __launch_bounds__(256) void gat_agg(const float* __restrict__ bias, int n) {
    __shared__ int   s_idx[8][32];
    __shared__ float s_ex [8][128];
    __shared__ float sbn[256];

    int tid  = threadIdx.x;
    int w    = tid >> 5;
    int lane = tid & 31;
    int head = lane >> 3;

    sbn[tid] = 0.f;
    __syncthreads();

    int d = blockIdx.x * 8 + w;
    if (d < n) {
        int beg = g_off[d];
        int deg = g_off[d + 1] - beg;
        float4 adv = ((const float4*)g_ad)[d];

        float4 sumex = make_float4(0.f, 0.f, 0.f, 0.f);
        float acc0 = 0.f, acc1 = 0.f, acc2 = 0.f, acc3 = 0.f;

        for (int base = 0; base < deg; base += 32) {
            int k = base + lane;
            if (k < deg) {
                int s = __ldcs(&g_csr[beg + k]);
                float4 e = f4lrelu(f4add(((const float4*)g_as)[s], adv));
                float4 ex = make_float4(__expf(e.x), __expf(e.y), __expf(e.z), __expf(e.w));
                sumex = f4add(sumex, ex);
                s_idx[w][lane] = s;
                *(float4*)&s_ex[w][lane * 4] = ex;
            }
            __syncwarp();
            int cnt = min(32, deg - base);
            if (cnt == 32) {
                #pragma unroll 8
                for (int j = 0; j < 32; j++) {
                    int   s  = s_idx[w][j];
                    float wt = s_ex[w][j * 4 + head];
                    uint2 pk = __ldcg((const uint2*)(&g_h[s * HD + lane * 4]));
                    __half2* hp = reinterpret_cast<__half2*>(&pk);
                    float2 f0 = __half22float2(hp[0]);
                    float2 f1 = __half22float2(hp[1]);
                    acc0 = fmaf(f0.x, wt, acc0);
                    acc1 = fmaf(f0.y, wt, acc1);
                    acc2 = fmaf(f1.x, wt, acc2);
                    acc3 = fmaf(f1.y, wt, acc3);
                }
            } else {
                #pragma unroll 4
                for (int j = 0; j < cnt; j++) {
                    int   s  = s_idx[w][j];
                    float wt = s_ex[w][j * 4 + head];
                    uint2 pk = __ldcg((const uint2*)(&g_h[s * HD + lane * 4]));
                    __half2* hp = reinterpret_cast<__half2*>(&pk);
                    float2 f0 = __half22float2(hp[0]);
                    float2 f1 = __half22float2(hp[1]);
                    acc0 = fmaf(f0.x, wt, acc0);
                    acc1 = fmaf(f0.y, wt, acc1);
                    acc2 = fmaf(f1.x, wt, acc2);
                    acc3 = fmaf(f1.y, wt, acc3);
                }
            }
            __syncwarp();
        }

        #pragma unroll
        for (int o = 16; o; o >>= 1) {
            sumex.x += __shfl_xor_sync(0xffffffffu, sumex.x, o);
            sumex.y += __shfl_xor_sync(0xffffffffu, sumex.y, o);
            sumex.z += __shfl_xor_sync(0xffffffffu, sumex.z, o);
            sumex.w += __shfl_xor_sync(0xffffffffu, sumex.w, o);
        }
        float sv = (head == 0) ? sumex.x : (head == 1) ? sumex.y
                 : (head == 2) ? sumex.z : sumex.w;
        float inv = 1.0f / (sv + 1e-16f);

        float4 b = *(const float4*)(bias + lane * 4);
        float o0 = fmaxf(fmaf(acc0, inv, b.x), 0.f);
        float o1 = fmaxf(fmaf(acc1, inv, b.y), 0.f);
        float o2 = fmaxf(fmaf(acc2, inv, b.z), 0.f);
        float o3 = fmaxf(fmaf(acc3, inv, b.w), 0.f);
        __stcs((float4*)(&g_x2[d * HD + lane * 4]), make_float4(o0, o1, o2, o3));

        int c = lane * 4;
        atomicAdd(&sbn[c + 0], o0);
        atomicAdd(&sbn[c + 1], o1);
        atomicAdd(&sbn[c + 2], o2);
        atomicAdd(&sbn[c + 3], o3);
        atomicAdd(&sbn[128 + c + 0], o0 * o0);
        atomicAdd(&sbn[128 + c + 1], o1 * o1);
        atomicAdd(&sbn[128 + c + 2], o2 * o2);
        atomicAdd(&sbn[128 + c + 3], o3 * o3);
    }
    __syncthreads();
    atomicAdd(&g_bn[tid], sbn[tid]);
}

// ---------------- BN finalize ----------------
__global__ void bn_final(const float* __restrict__ gamma, const float* __restrict__ beta, int n) {
    int c = threadIdx.x;
    float fn = (float)n;
    float mu  = g_bn[c] / fn;
    float var = g_bn[HD + c] / fn - mu * mu;
    float inv = rsqrtf(var + 1e-5f);
    float sc  = gamma[c] * inv;
    g_scale[c] = sc;
    g_shift[c] = beta[c] - mu * sc;
    g_bn[c] = 0.f;
    g_bn[HD + c] = 0.f;
}

// ---------------- pooling: batch sorted -> segmented register accumulation ----------------
__global__ __launch_bounds__(128) void pool_kernel(const int* __restrict__ batch, int n, int chunk) {
    int i0 = blockIdx.x * chunk;
    if (i0 >= n) return;
    int i1 = min(n, i0 + chunk);
    int t  = threadIdx.x;
    float acc = 0.f;
    int cur = batch[i0];
    int run = 0;
    for (int i = i0; i < i1; i++) {
        int g = batch[i];
        if (g != cur) {
            atomicAdd(&g_pool[cur * HD + t], acc);
            if (t == 0) atomicAdd(&g_cnt[cur], run);
            acc = 0.f; run = 0; cur = g;
        }
        acc += __ldcs(&g_x2[i * HD + t]);
        run++;
    }
    atomicAdd(&g_pool[cur * HD + t], acc);
    if (t == 0) atomicAdd(&g_cnt[cur], run);
}

// ---------------- MLP head ----------------
__global__ __launch_bounds__(128) void head_kernel(const float* __restrict__ L1W,
                                                   const float* __restrict__ L1b,
                                                   const float* __restrict__ L2W,
                                                   const float* __restrict__ L2b,
                                                   float* __restrict__ out) {
    int g = blockIdx.x, t = threadIdx.x;
    __shared__ float p[128], r0[128], r1[128];
    int c = g_cnt[g];
    float denom = (float)(c > 0 ? c : 1);
    p[t] = fmaf(g_pool[g * HD + t] / denom, g_scale[t], g_shift[t]);
    g_pool[g * HD + t] = 0.f;
    if (t == 0) g_cnt[g] = 0;
    __syncthreads();
    float acc = L1b[t];
    #pragma unroll 8
    for (int k = 0; k < 128; k++)
        acc = fmaf(p[k], L1W[k * HD + t], acc);
    float z = fmaxf(acc, 0.f);
    r0[t] = z * L2W[t * 2 + 0];
    r1[t] = z * L2W[t * 2 + 1];
    __syncthreads();
    for (int o = 64; o; o >>= 1) {
        if (t < o) { r0[t] += r0[t + o]; r1[t] += r1[t + o]; }
        __syncthreads();
    }
    if (t == 0) {
        out[g * 2 + 0] = r0[0] + L2b[0];
        out[g * 2 + 1] = r1[0] + L2b[1];
    }
}

// ---------------- launch: CSR build forked onto a side stream, overlapping gemm1 ----------------
extern "C" void kernel_launch(void* const* d_in, const int* in_sizes, int n_in,
                              void* d_out, int out_size) {
    const float* x    = (const float*)d_in[0];
    const int*   ei   = (const int*)  d_in[1];
    const int*   batch= (const int*)  d_in[2];
    const float* W1   = (const float*)d_in[3];
    const float* a1s  = (const float*)d_in[4];
    const float* a1d  = (const float*)d_in[5];
    const float* b1   = (const float*)d_in[6];
    const float* bn1g = (const float*)d_in[7];
    const float* bn1b = (const float*)d_in[8];
    const float* W2   = (const float*)d_in[9];
    const float* a2s  = (const float*)d_in[10];
    const float* a2d  = (const float*)d_in[11];
    const float* b2   = (const float*)d_in[12];
    const float* bn2g = (const float*)d_in[13];
    const float* bn2b = (const float*)d_in[14];
    const float* L1W  = (const float*)d_in[15];
    const float* L1b  = (const float*)d_in[16];
    const float* L2W  = (const float*)d_in[17];
    const float* L2b  = (const float*)d_in[18];

    int n = in_sizes[0] / HD;
    int E = in_sizes[1] / 2;
    int G = out_size / 2;
    int ET = E + n;

    int gb  = (n + 63) / 64;
    int agb = (n + 7) / 8;

    cudaStream_t sB;
    cudaStreamCreateWithFlags(&sB, cudaStreamNonBlocking);
    cudaEvent_t eFork, eJoin;
    cudaEventCreateWithFlags(&eFork, cudaEventDisableTiming);
    cudaEventCreateWithFlags(&eJoin, cudaEventDisableTiming);

    // fork: CSR build on side stream, concurrent with gemm1 on the main (capture) stream
    cudaEventRecord(eFork, 0);
    cudaStreamWaitEvent(sB, eFork, 0);
    count_kernel<<<(ET + 255) / 256, 256, 0, sB>>>(ei, E, n);
    scan_kernel <<<1, 1024, 0, sB>>>(n);
    fill_kernel <<<(ET + 255) / 256, 256, 0, sB>>>(ei, E, n);
    cudaEventRecord(eJoin, sB);

    gemm_tc<<<gb, 256>>>(x, W1, n, 0, 0, a1s, a1d);

    // join: gat_agg needs both CSR and gemm1
    cudaStreamWaitEvent(0, eJoin, 0);

    gat_agg <<<agb, 256>>>(b1, n);
    bn_final<<<1, 128>>>(bn1g, bn1b, n);

    gemm_tc <<<gb, 256>>>(nullptr, W2, n, 1, 1, a2s, a2d);
    gat_agg <<<agb, 256>>>(b2, n);
    bn_final<<<1, 128>>>(bn2g, bn2b, n);

    pool_kernel<<<(n + 255) / 256, 128>>>(batch, n, 256);
    head_kernel<<<G, 128>>>(L1W, L1b, L2W, L2b, (float*)d_out);

    cudaEventDestroy(eFork);
    cudaEventDestroy(eJoin);
    cudaStreamDestroy(sB);
}

// round 14
// speedup vs baseline: 1.0281x; 1.0010x over previous
#include <cuda_runtime.h>
#include <cuda_fp16.h>
#include <math.h>

#define DIN 128
#define HD  128
#define NH  4
#define NMAX 50000
#define ET_MAX 1700000   // E + N self loops
#define GMAX 256
#define KC   32          // GEMM K-chunk in smem

// ---------------- scratch (static device globals; no allocation) ----------------
__device__ __half g_h [NMAX * HD];    // GEMM output (pre-attention features), fp16 payload
__device__ float g_x2[NMAX * HD];     // layer output / next layer input
__device__ float g_as[NMAX * NH];
__device__ float g_ad[NMAX * NH];
__device__ int   g_deg[NMAX];
__device__ int   g_off[NMAX + 1];
__device__ int   g_cur[NMAX];
__device__ int   g_csr[ET_MAX];
__device__ float g_bn[2 * HD];        // col sum, col sumsq (zero-init, reset by bn_final)
__device__ float g_scale[HD];
__device__ float g_shift[HD];
__device__ float g_w2[HD * HD];       // BN1-folded W2
__device__ float g_wv[HD];            // shift^T @ W2 (column bias for layer-2 gemm)
__device__ float g_v0[HD];            // zero vector (never written)
__device__ float g_pool[GMAX * HD];   // zero-init, reset by head kernel
__device__ int   g_cnt[GMAX];

// ---------------- helpers ----------------
__device__ __forceinline__ float4 f4add(float4 a, float4 b) {
    return make_float4(a.x + b.x, a.y + b.y, a.z + b.z, a.w + b.w);
}
__device__ __forceinline__ float4 f4lrelu(float4 v) {
    return make_float4(fmaxf(v.x, 0.2f * v.x), fmaxf(v.y, 0.2f * v.y),
                       fmaxf(v.z, 0.2f * v.z), fmaxf(v.w, 0.2f * v.w));
}
__device__ __forceinline__ void mma_tf32(float c[4], const float a[4], float b0, float b1) {
    asm volatile(
        "mma.sync.aligned.m16n8k8.row.col.f32.tf32.tf32.f32 "
        "{%0,%1,%2,%3}, {%4,%5,%6,%7}, {%8,%9}, {%0,%1,%2,%3};"
        : "+f"(c[0]), "+f"(c[1]), "+f"(c[2]), "+f"(c[3])
        : "r"(__float_as_uint(a[0])), "r"(__float_as_uint(a[1])),
          "r"(__float_as_uint(a[2])), "r"(__float_as_uint(a[3])),
          "r"(__float_as_uint(b0)),   "r"(__float_as_uint(b1)));
}
__device__ __forceinline__ void cp_async16(unsigned smem_addr, const void* gptr) {
    asm volatile("cp.async.cg.shared.global [%0], [%1], 16;\n"
                 :: "r"(smem_addr), "l"(gptr));
}
__device__ __forceinline__ void cp_commit() {
    asm volatile("cp.async.commit_group;\n");
}
template <int N>
__device__ __forceinline__ void cp_wait() {
    asm volatile("cp.async.wait_group %0;\n" :: "n"(N));
}

// ---------------- CSR build ----------------
__global__ void count_kernel(const int* __restrict__ ei, int E, int n) {
    int i = blockIdx.x * blockDim.x + threadIdx.x;
    if (i >= E + n) return;
    int d = (i < E) ? ei[E + i] : (i - E);
    atomicAdd(&g_deg[d], 1);
}

// single-block exclusive scan of g_deg -> g_off, 4 elems/thread.
// Also zeroes g_deg (for next call) and g_cur (for fill later this call).
__global__ void scan_kernel(int n) {
    __shared__ int warp_sums[32];
    __shared__ int carry_sh;
    int t = threadIdx.x;
    int lane = t & 31, wid = t >> 5;
    if (t == 0) { carry_sh = 0; g_off[0] = 0; }
    __syncthreads();
    for (int base = 0; base < n; base += 4096) {
        int i = base + t * 4;
        int v0 = 0, v1 = 0, v2 = 0, v3 = 0;
        if (i + 3 < n) {
            int4 v = *(const int4*)&g_deg[i];
            v0 = v.x; v1 = v.y; v2 = v.z; v3 = v.w;
        } else {
            if (i     < n) v0 = g_deg[i];
            if (i + 1 < n) v1 = g_deg[i + 1];
            if (i + 2 < n) v2 = g_deg[i + 2];
            if (i + 3 < n) v3 = g_deg[i + 3];
        }
        int p0 = v0, p1 = p0 + v1, p2 = p1 + v2, p3 = p2 + v3;
        int x = p3;
        #pragma unroll
        for (int o = 1; o < 32; o <<= 1) {
            int y = __shfl_up_sync(0xffffffffu, x, o);
            if (lane >= o) x += y;
        }
        if (lane == 31) warp_sums[wid] = x;
        __syncthreads();
        if (wid == 0) {
            int w = warp_sums[lane];
            #pragma unroll
            for (int o = 1; o < 32; o <<= 1) {
                int y = __shfl_up_sync(0xffffffffu, w, o);
                if (lane >= o) w += y;
            }
            warp_sums[lane] = w;
        }
        __syncthreads();
        int woff = (wid > 0) ? warp_sums[wid - 1] : 0;
        int excl = carry_sh + woff + (x - p3);
        if (i     < n) g_off[i + 1] = excl + p0;
        if (i + 1 < n) g_off[i + 2] = excl + p1;
        if (i + 2 < n) g_off[i + 3] = excl + p2;
        if (i + 3 < n) g_off[i + 4] = excl + p3;
        int4 z4 = make_int4(0, 0, 0, 0);
        if (i + 3 < n) {
            *(int4*)&g_deg[i] = z4;
            *(int4*)&g_cur[i] = z4;
        } else {
            for (int q = 0; q < 4; q++)
                if (i + q < n) { g_deg[i + q] = 0; g_cur[i + q] = 0; }
        }
        __syncthreads();
        if (t == 1023) carry_sh = excl + p3;
        __syncthreads();
    }
}

__global__ void fill_kernel(const int* __restrict__ ei, int E, int n) {
    int i = blockIdx.x * blockDim.x + threadIdx.x;
    if (i >= E + n) return;
    int s, d;
    if (i < E) { s = __ldcs(&ei[i]); d = __ldcs(&ei[E + i]); }
    else       { s = d = i - E; }
    int pos = g_off[d] + atomicAdd(&g_cur[d], 1);
    g_csr[pos] = s;
}

// ---------------- fold BN1 affine into W2: g_w2 = diag(scale)W2, g_wv = shift^T W2 ----------------
__global__ void fold_w2(const float* __restrict__ W2) {
    __shared__ float part[2][128];
    int t = threadIdx.x;
    int nc = t & 127;
    int hf = t >> 7;
    float v = 0.f;
    for (int k = hf * 64; k < hf * 64 + 64; k++) {
        float w = W2[k * 128 + nc];
        g_w2[k * 128 + nc] = g_scale[k] * w;
        v = fmaf(g_shift[k], w, v);
    }
    part[hf][nc] = v;
    __syncthreads();
    if (hf == 0) g_wv[nc] = part[0][nc] + part[1][nc];
}

// ---------------- tensor-core GEMM (tf32 mma.sync, cp.async pipelined) ----------------
// g_h[M,128](fp16) = A @ B (+ column bias v), fused per-head attention logits.
// 64-row tiles, 8 warps of 16x64, 2-stage cp.async pipeline over 4 K-chunks.
__global__ __launch_bounds__(256, 3) void gemm_tc(const float* __restrict__ Ain,
                                                  const float* __restrict__ Bin,
                                                  int M, int use_x2, int use_w2, int use_v,
                                                  const float* __restrict__ a_src,
                                                  const float* __restrict__ a_dst) {
    const float* A = use_x2 ? (const float*)g_x2 : Ain;
    const float* B = use_w2 ? (const float*)g_w2 : Bin;
    const float* vv = use_v ? (const float*)g_wv : (const float*)g_v0;

    __shared__ float As[2][64][36];     // stride 36 floats = 144B (16B aligned)
    __shared__ float Bs[2][KC][132];    // stride 132 floats = 528B (16B aligned)
    __shared__ float sA[64][NH];
    __shared__ float sD[64][NH];

    int tid  = threadIdx.x;
    int lane = tid & 31;
    int warp = tid >> 5;
    int warpM = warp >> 1;
    int warpN = warp & 1;
    int row0 = blockIdx.x * 64;

    sA[tid >> 2][tid & 3] = 0.f;
    sD[tid >> 2][tid & 3] = 0.f;

    float c[8][4];
    #pragma unroll
    for (int j = 0; j < 8; j++)
        #pragma unroll
        for (int q = 0; q < 4; q++) c[j][q] = 0.f;

    // A-copy slots: 512 16B copies; this thread's two slots
    int ar0 = (tid * 2)     >> 3, akq0 = (tid * 2)     & 7;
    int ar1 = (tid * 2 + 1) >> 3, akq1 = (tid * 2 + 1) & 7;
    bool av0 = (row0 + ar0) < M;
    bool av1 = (row0 + ar1) < M;

    auto issue = [&](int kc, int st) {
        if (av0)
            cp_async16((unsigned)__cvta_generic_to_shared(&As[st][ar0][akq0 * 4]),
                       A + (row0 + ar0) * 128 + kc + akq0 * 4);
        if (av1)
            cp_async16((unsigned)__cvta_generic_to_shared(&As[st][ar1][akq1 * 4]),
                       A + (row0 + ar1) * 128 + kc + akq1 * 4);
        #pragma unroll
        for (int i = 0; i < 4; i++) {
            int slot = tid + i * 256;
            int k  = slot >> 5;
            int nq = slot & 31;
            cp_async16((unsigned)__cvta_generic_to_shared(&Bs[st][k][nq * 4]),
                       B + (kc + k) * 128 + nq * 4);
        }
        cp_commit();
    };

    issue(0, 0);
    #pragma unroll
    for (int cidx = 0; cidx < 4; cidx++) {
        int st = cidx & 1;
        if (cidx + 1 < 4) {
            issue((cidx + 1) * KC, st ^ 1);
            cp_wait<1>();
        } else {
            cp_wait<0>();
        }
        __syncthreads();

        #pragma unroll
        for (int ks = 0; ks < KC; ks += 8) {
            float a[4];
            int ar = warpM * 16 + (lane >> 2);
            int ac = ks + (lane & 3);
            a[0] = As[st][ar][ac];
            a[1] = As[st][ar + 8][ac];
            a[2] = As[st][ar][ac + 4];
            a[3] = As[st][ar + 8][ac + 4];
            #pragma unroll
            for (int j = 0; j < 8; j++) {
                int bn = warpN * 64 + j * 8 + (lane >> 2);
                float b0 = Bs[st][ks + (lane & 3)][bn];
                float b1 = Bs[st][ks + (lane & 3) + 4][bn];
                mma_tf32(c[j], a, b0, b1);
            }
        }
        __syncthreads();
    }

    // epilogue: column bias + fp16 store + fused attention logit partials
    {
        int lr0 = warpM * 16 + (lane >> 2);
        int lr1 = lr0 + 8;
        int rr0 = row0 + lr0;
        int rr1 = row0 + lr1;
        float ps0[2] = {0.f, 0.f}, pd0[2] = {0.f, 0.f};
        float ps1[2] = {0.f, 0.f}, pd1[2] = {0.f, 0.f};
        #pragma unroll
        for (int j = 0; j < 8; j++) {
            int cn = warpN * 64 + j * 8 + (lane & 3) * 2;
            float v0 = __ldg(&vv[cn]), v1 = __ldg(&vv[cn + 1]);
            c[j][0] += v0; c[j][1] += v1;
            c[j][2] += v0; c[j][3] += v1;
            float s0 = a_src[cn], s1 = a_src[cn + 1];
            float d0 = a_dst[cn], d1 = a_dst[cn + 1];
            int hh = j >> 2;
            ps0[hh] = fmaf(c[j][0], s0, fmaf(c[j][1], s1, ps0[hh]));
            pd0[hh] = fmaf(c[j][0], d0, fmaf(c[j][1], d1, pd0[hh]));
            ps1[hh] = fmaf(c[j][2], s0, fmaf(c[j][3], s1, ps1[hh]));
            pd1[hh] = fmaf(c[j][2], d0, fmaf(c[j][3], d1, pd1[hh]));
            if (rr0 < M)
                *(__half2*)(&g_h[rr0 * 128 + cn]) = __floats2half2_rn(c[j][0], c[j][1]);
            if (rr1 < M)
                *(__half2*)(&g_h[rr1 * 128 + cn]) = __floats2half2_rn(c[j][2], c[j][3]);
        }
        int h0 = warpN * 2;
        if (rr0 < M) {
            atomicAdd(&sA[lr0][h0],     ps0[0]);
            atomicAdd(&sA[lr0][h0 + 1], ps0[1]);
            atomicAdd(&sD[lr0][h0],     pd0[0]);
            atomicAdd(&sD[lr0][h0 + 1], pd0[1]);
        }
        if (rr1 < M) {
            atomicAdd(&sA[lr1][h0],     ps1[0]);
            atomicAdd(&sA[lr1][h0 + 1], ps1[1]);
            atomicAdd(&sD[lr1][h0],     pd1[0]);
            atomicAdd(&sD[lr1][h0 + 1], pd1[1]);
        }
    }
    __syncthreads();
    {
        int r = tid >> 2, h = tid & 3;
        if (row0 + r < M) {
            g_as[(row0 + r) * NH + h] = sA[r][h];
            g_ad[(row0 + r) * NH + h] = sD[r][h];
        }
    }
}

// ---------------- GAT aggregation: one WARP per dst node + fused BN stats ----------------
__global__ __launch_bounds__(256) void gat_agg(const float* __restrict__ bias, int n) {
    __shared__ int   s_idx[8][32];
    __shared__ float s_ex [8][128];
    __shared__ float sbn[256];

    int tid  = threadIdx.x;
    int w    = tid >> 5;
    int lane = tid & 31;
    int head = lane >> 3;

    sbn[tid] = 0.f;
    __syncthreads();

    int d = blockIdx.x * 8 + w;
    if (d < n) {
        int beg = g_off[d];
        int deg = g_off[d + 1] - beg;
        float4 adv = ((const float4*)g_ad)[d];

        float4 sumex = make_float4(0.f, 0.f, 0.f, 0.f);
        float acc0 = 0.f, acc1 = 0.f, acc2 = 0.f, acc3 = 0.f;

        for (int base = 0; base < deg; base += 32) {
            int k = base + lane;
            if (k < deg) {
                int s = __ldcs(&g_csr[beg + k]);
                float4 e = f4lrelu(f4add(((const float4*)g_as)[s], adv));
                float4 ex = make_float4(__expf(e.x), __expf(e.y), __expf(e.z), __expf(e.w));
                sumex = f4add(sumex, ex);
                s_idx[w][lane] = s;
                *(float4*)&s_ex[w][lane * 4] = ex;
            }
            __syncwarp();
            int cnt = min(32, deg - base);
            if (cnt == 32) {
                #pragma unroll 8
                for (int j = 0; j < 32; j++) {
                    int   s  = s_idx[w][j];
                    float wt = s_ex[w][j * 4 + head];
                    uint2 pk = __ldcg((const uint2*)(&g_h[s * HD + lane * 4]));
                    __half2* hp = reinterpret_cast<__half2*>(&pk);
                    float2 f0 = __half22float2(hp[0]);
                    float2 f1 = __half22float2(hp[1]);
                    acc0 = fmaf(f0.x, wt, acc0);
                    acc1 = fmaf(f0.y, wt, acc1);
                    acc2 = fmaf(f1.x, wt, acc2);
                    acc3 = fmaf(f1.y, wt, acc3);
                }
            } else {
                #pragma unroll 4
                for (int j = 0; j < cnt; j++) {
                    int   s  = s_idx[w][j];
                    float wt = s_ex[w][j * 4 + head];
                    uint2 pk = __ldcg((const uint2*)(&g_h[s * HD + lane * 4]));
                    __half2* hp = reinterpret_cast<__half2*>(&pk);
                    float2 f0 = __half22float2(hp[0]);
                    float2 f1 = __half22float2(hp[1]);
                    acc0 = fmaf(f0.x, wt, acc0);
                    acc1 = fmaf(f0.y, wt, acc1);
                    acc2 = fmaf(f1.x, wt, acc2);
                    acc3 = fmaf(f1.y, wt, acc3);
                }
            }
            __syncwarp();
        }

        #pragma unroll
        for (int o = 16; o; o >>= 1) {
            sumex.x += __shfl_xor_sync(0xffffffffu, sumex.x, o);
            sumex.y += __shfl_xor_sync(0xffffffffu, sumex.y, o);
            sumex.z += __shfl_xor_sync(0xffffffffu, sumex.z, o);
            sumex.w += __shfl_xor_sync(0xffffffffu, sumex.w, o);
        }
        float sv = (head == 0) ? sumex.x : (head == 1) ? sumex.y
                 : (head == 2) ? sumex.z : sumex.w;
        float inv = 1.0f / (sv + 1e-16f);

        float4 b = *(const float4*)(bias + lane * 4);
        float o0 = fmaxf(fmaf(acc0, inv, b.x), 0.f);
        float o1 = fmaxf(fmaf(acc1, inv, b.y), 0.f);
        float o2 = fmaxf(fmaf(acc2, inv, b.z), 0.f);
        float o3 = fmaxf(fmaf(acc3, inv, b.w), 0.f);
        __stcs((float4*)(&g_x2[d * HD + lane * 4]), make_float4(o0, o1, o2, o3));

        int c = lane * 4;
        atomicAdd(&sbn[c + 0], o0);
        atomicAdd(&sbn[c + 1], o1);
        atomicAdd(&sbn[c + 2], o2);
        atomicAdd(&sbn[c + 3], o3);
        atomicAdd(&sbn[128 + c + 0], o0 * o0);
        atomicAdd(&sbn[128 + c + 1], o1 * o1);
        atomicAdd(&sbn[128 + c + 2], o2 * o2);
        atomicAdd(&sbn[128 + c + 3], o3 * o3);
    }
    __syncthreads();
    atomicAdd(&g_bn[tid], sbn[tid]);
}

// ---------------- BN finalize ----------------
__global__ void bn_final(const float* __restrict__ gamma, const float* __restrict__ beta, int n) {
    int c = threadIdx.x;
    float fn = (float)n;
    float mu  = g_bn[c] / fn;
    float var = g_bn[HD + c] / fn - mu * mu;
    float inv = rsqrtf(var + 1e-5f);
    float sc  = gamma[c] * inv;
    g_scale[c] = sc;
    g_shift[c] = beta[c] - mu * sc;
    g_bn[c] = 0.f;
    g_bn[HD + c] = 0.f;
}

// ---------------- pooling: batch sorted -> segmented register accumulation ----------------
__global__ __launch_bounds__(128) void pool_kernel(const int* __restrict__ batch, int n, int chunk) {
    int i0 = blockIdx.x * chunk;
    if (i0 >= n) return;
    int i1 = min(n, i0 + chunk);
    int t  = threadIdx.x;
    float acc = 0.f;
    int cur = batch[i0];
    int run = 0;
    for (int i = i0; i < i1; i++) {
        int g = batch[i];
        if (g != cur) {
            atomicAdd(&g_pool[cur * HD + t], acc);
            if (t == 0) atomicAdd(&g_cnt[cur], run);
            acc = 0.f; run = 0; cur = g;
        }
        acc += __ldcs(&g_x2[i * HD + t]);
        run++;
    }
    atomicAdd(&g_pool[cur * HD + t], acc);
    if (t == 0) atomicAdd(&g_cnt[cur], run);
}

// ---------------- MLP head ----------------
__global__ __launch_bounds__(128) void head_kernel(const float* __restrict__ L1W,
                                                   const float* __restrict__ L1b,
                                                   const float* __restrict__ L2W,
                                                   const float* __restrict__ L2b,
                                                   float* __restrict__ out) {
    int g = blockIdx.x, t = threadIdx.x;
    __shared__ float p[128], r0[128], r1[128];
    int c = g_cnt[g];
    float denom = (float)(c > 0 ? c : 1);
    p[t] = fmaf(g_pool[g * HD + t] / denom, g_scale[t], g_shift[t]);
    g_pool[g * HD + t] = 0.f;
    if (t == 0) g_cnt[g] = 0;
    __syncthreads();
    float acc = L1b[t];
    #pragma unroll 8
    for (int k = 0; k < 128; k++)
        acc = fmaf(p[k], L1W[k * HD + t], acc);
    float z = fmaxf(acc, 0.f);
    r0[t] = z * L2W[t * 2 + 0];
    r1[t] = z * L2W[t * 2 + 1];
    __syncthreads();
    for (int o = 64; o; o >>= 1) {
        if (t < o) { r0[t] += r0[t + o]; r1[t] += r1[t + o]; }
        __syncthreads();
    }
    if (t == 0) {
        out[g * 2 + 0] = r0[0] + L2b[0];
        out[g * 2 + 1] = r1[0] + L2b[1];
    }
}

// ---------------- launch: CSR build forked onto a side stream, overlapping gemm1 ----------------
extern "C" void kernel_launch(void* const* d_in, const int* in_sizes, int n_in,
                              void* d_out, int out_size) {
    const float* x    = (const float*)d_in[0];
    const int*   ei   = (const int*)  d_in[1];
    const int*   batch= (const int*)  d_in[2];
    const float* W1   = (const float*)d_in[3];
    const float* a1s  = (const float*)d_in[4];
    const float* a1d  = (const float*)d_in[5];
    const float* b1   = (const float*)d_in[6];
    const float* bn1g = (const float*)d_in[7];
    const float* bn1b = (const float*)d_in[8];
    const float* W2   = (const float*)d_in[9];
    const float* a2s  = (const float*)d_in[10];
    const float* a2d  = (const float*)d_in[11];
    const float* b2   = (const float*)d_in[12];
    const float* bn2g = (const float*)d_in[13];
    const float* bn2b = (const float*)d_in[14];
    const float* L1W  = (const float*)d_in[15];
    const float* L1b  = (const float*)d_in[16];
    const float* L2W  = (const float*)d_in[17];
    const float* L2b  = (const float*)d_in[18];

    int n = in_sizes[0] / HD;
    int E = in_sizes[1] / 2;
    int G = out_size / 2;
    int ET = E + n;

    int gb  = (n + 63) / 64;
    int agb = (n + 7) / 8;

    cudaStream_t sB;
    cudaStreamCreateWithFlags(&sB, cudaStreamNonBlocking);
    cudaEvent_t eFork, eJoin;
    cudaEventCreateWithFlags(&eFork, cudaEventDisableTiming);
    cudaEventCreateWithFlags(&eJoin, cudaEventDisableTiming);

    // fork: CSR build on side stream, concurrent with gemm1 on the main (capture) stream
    cudaEventRecord(eFork, 0);
    cudaStreamWaitEvent(sB, eFork, 0);
    count_kernel<<<(ET + 255) / 256, 256, 0, sB>>>(ei, E, n);
    scan_kernel <<<1, 1024, 0, sB>>>(n);
    fill_kernel <<<(ET + 255) / 256, 256, 0, sB>>>(ei, E, n);
    cudaEventRecord(eJoin, sB);

    gemm_tc<<<gb, 256>>>(x, W1, n, 0, 0, 0, a1s, a1d);

    // join: gat_agg needs both CSR and gemm1
    cudaStreamWaitEvent(0, eJoin, 0);

    gat_agg <<<agb, 256>>>(b1, n);
    bn_final<<<1, 128>>>(bn1g, bn1b, n);
    fold_w2 <<<1, 256>>>(W2);

    gemm_tc <<<gb, 256>>>(nullptr, nullptr, n, 1, 1, 1, a2s, a2d);
    gat_agg <<<agb, 256>>>(b2, n);
    bn_final<<<1, 128>>>(bn2g, bn2b, n);

    pool_kernel<<<(n + 255) / 256, 128>>>(batch, n, 256);
    head_kernel<<<G, 128>>>(L1W, L1b, L2W, L2b, (float*)d_out);

    cudaEventDestroy(eFork);
    cudaEventDestroy(eJoin);
    cudaStreamDestroy(sB);
}